// round 2
// baseline (speedup 1.0000x reference)
#include <cuda_runtime.h>

#define RADIUS_F 5.0f
#define ECONV_F  14.399645f
#define MAX_ATOMS_COMB 262144
#define MOL_BITS 11
#define MOL_MASK 0x7FFu

// Packed per-atom record: charge (f32, low 11 mantissa bits rounded away)
// with mol index stored in those low 11 bits. One 4B gather gives qi+mol.
__device__ unsigned g_comb4[MAX_ATOMS_COMB];
// Fallback: full-precision pair (charge, mol) if n_mol > 2048.
__device__ float2   g_comb8[MAX_ATOMS_COMB];

__global__ void prep_kernel(const float* __restrict__ charges,
                            const int*   __restrict__ mol_index,
                            int n_atoms, int mode,   // 0=packed4, 1=comb8
                            float* __restrict__ out, int n_mol)
{
    int i = blockIdx.x * blockDim.x + threadIdx.x;
    if (i < n_atoms) {
        if (mode == 0) {
            unsigned b = __float_as_uint(charges[i]);
            // round-to-nearest on the 11 bits we steal (carry into exponent is fine)
            b += 0x400u;
            b &= ~MOL_MASK;
            g_comb4[i] = b | (unsigned)mol_index[i];
        } else {
            float2 c;
            c.x = charges[i];
            c.y = __int_as_float(mol_index[i]);
            g_comb8[i] = c;
        }
    }
    if (i < n_mol) out[i] = 0.0f;
}

template <bool PACKED>
__device__ __forceinline__ void accum_pair(
    float r, int fi, int si,
    const float* __restrict__ charges,
    float* __restrict__ bins)
{
    if (r < RADIUS_F) {
        float qi; int mol;
        if (PACKED) {
            unsigned b = g_comb4[fi];
            mol = (int)(b & MOL_MASK);
            qi  = __uint_as_float(b & ~MOL_MASK);
        } else {
            float2 c = g_comb8[fi];
            qi  = c.x;
            mol = __float_as_int(c.y);
        }
        float qj  = __ldg(charges + si);
        float scr = 0.5f * (1.0f + cospif(r * (1.0f / RADIUS_F)));
        float e   = qi * qj * __fdividef(scr, r);
        atomicAdd(bins + mol, e);
    }
}

template <bool PACKED>
__global__ void __launch_bounds__(1024, 2)
pair_kernel(const float* __restrict__ pair_dist,
            const int*   __restrict__ pair_first,
            const int*   __restrict__ pair_second,
            const float* __restrict__ charges,
            float* __restrict__ out,
            int n_pairs, int n_mol)
{
    extern __shared__ float bins[];
    for (int b = threadIdx.x; b < n_mol; b += blockDim.x) bins[b] = 0.0f;
    __syncthreads();

    const int gtid   = blockIdx.x * blockDim.x + threadIdx.x;
    const int stride = gridDim.x * blockDim.x;
    const int n4     = n_pairs >> 2;

    const float4* __restrict__ pd4 = (const float4*)pair_dist;
    const int4*   __restrict__ pf4 = (const int4*)pair_first;
    const int4*   __restrict__ ps4 = (const int4*)pair_second;

    int i = gtid;
    // unroll-2 over quads: two independent dense LDG.128 batches in flight
    for (; i + stride < n4; i += 2 * stride) {
        float4 dA = __ldcs(pd4 + i);
        int4   fA = __ldcs(pf4 + i);
        int4   sA = __ldcs(ps4 + i);
        int    j  = i + stride;
        float4 dB = __ldcs(pd4 + j);
        int4   fB = __ldcs(pf4 + j);
        int4   sB = __ldcs(ps4 + j);

        accum_pair<PACKED>(dA.x, fA.x, sA.x, charges, bins);
        accum_pair<PACKED>(dA.y, fA.y, sA.y, charges, bins);
        accum_pair<PACKED>(dA.z, fA.z, sA.z, charges, bins);
        accum_pair<PACKED>(dA.w, fA.w, sA.w, charges, bins);
        accum_pair<PACKED>(dB.x, fB.x, sB.x, charges, bins);
        accum_pair<PACKED>(dB.y, fB.y, sB.y, charges, bins);
        accum_pair<PACKED>(dB.z, fB.z, sB.z, charges, bins);
        accum_pair<PACKED>(dB.w, fB.w, sB.w, charges, bins);
    }
    for (; i < n4; i += stride) {
        float4 d = __ldcs(pd4 + i);
        int4   f = __ldcs(pf4 + i);
        int4   s = __ldcs(ps4 + i);
        accum_pair<PACKED>(d.x, f.x, s.x, charges, bins);
        accum_pair<PACKED>(d.y, f.y, s.y, charges, bins);
        accum_pair<PACKED>(d.z, f.z, s.z, charges, bins);
        accum_pair<PACKED>(d.w, f.w, s.w, charges, bins);
    }
    // tail (n_pairs not divisible by 4)
    for (int t = (n4 << 2) + gtid; t < n_pairs; t += stride) {
        accum_pair<PACKED>(pair_dist[t], pair_first[t], pair_second[t],
                           charges, bins);
    }

    __syncthreads();
    for (int b = threadIdx.x; b < n_mol; b += blockDim.x) {
        atomicAdd(out + b, 0.5f * ECONV_F * bins[b]);
    }
}

// Fallback if n_mol too large for shared privatization or n_atoms > scratch.
__global__ void pair_kernel_global(const float* __restrict__ pair_dist,
                                   const int*   __restrict__ pair_first,
                                   const int*   __restrict__ pair_second,
                                   const float* __restrict__ charges,
                                   const int*   __restrict__ mol_index,
                                   float* __restrict__ out, int n_pairs)
{
    const int gtid   = blockIdx.x * blockDim.x + threadIdx.x;
    const int stride = gridDim.x * blockDim.x;
    for (int i = gtid; i < n_pairs; i += stride) {
        float r = pair_dist[i];
        if (r < RADIUS_F) {
            int   fi  = pair_first[i];
            float qi  = __ldg(charges + fi);
            int   mol = __ldg(mol_index + fi);
            float qj  = __ldg(charges + pair_second[i]);
            float scr = 0.5f * (1.0f + cospif(r * (1.0f / RADIUS_F)));
            float e   = 0.5f * ECONV_F * qi * qj * __fdividef(scr, r);
            atomicAdd(out + mol, e);
        }
    }
}

extern "C" void kernel_launch(void* const* d_in, const int* in_sizes, int n_in,
                              void* d_out, int out_size)
{
    const float* charges     = (const float*)d_in[0];
    const float* pair_dist   = (const float*)d_in[1];
    const int*   pair_first  = (const int*)d_in[2];
    const int*   pair_second = (const int*)d_in[3];
    const int*   mol_index   = (const int*)d_in[4];

    int n_atoms = in_sizes[0];
    int n_pairs = in_sizes[1];
    int n_mol   = out_size;
    float* out  = (float*)d_out;

    bool comb_ok  = (n_atoms <= MAX_ATOMS_COMB);
    bool packable = comb_ok && (n_mol <= (1 << MOL_BITS));
    size_t smem   = (size_t)n_mol * sizeof(float);
    bool smem_ok  = (smem <= 48 * 1024);

    int prep_n = n_atoms > n_mol ? n_atoms : n_mol;
    prep_kernel<<<(prep_n + 255) / 256, 256>>>(charges, mol_index, n_atoms,
                                               packable ? 0 : 1, out, n_mol);

    const int threads = 1024;
    const int blocks  = 296;  // 2 CTAs/SM on 148 SMs

    if (comb_ok && smem_ok) {
        if (packable)
            pair_kernel<true><<<blocks, threads, smem>>>(
                pair_dist, pair_first, pair_second, charges,
                out, n_pairs, n_mol);
        else
            pair_kernel<false><<<blocks, threads, smem>>>(
                pair_dist, pair_first, pair_second, charges,
                out, n_pairs, n_mol);
    } else {
        pair_kernel_global<<<blocks, threads>>>(
            pair_dist, pair_first, pair_second, charges, mol_index,
            out, n_pairs);
    }
}